// round 3
// baseline (speedup 1.0000x reference)
#include <cuda_runtime.h>

// Problem constants (z: [8192, 20, 256] f32, labels: [8192] i32, K=10)
#define NUM_LABELS 10
#define B_ROWS     8192
#define CH         5120          // C*H = 20*256
#define EPS        1e-8f

#define TPB            128       // threads per CTA in accumulate kernel
#define COLS_PER_CTA   512       // TPB * 4 (float4 per thread)
#define ROWS_PER_CHUNK 128
#define COL_BLOCKS     (CH / COLS_PER_CTA)          // 10
#define ROW_CHUNKS     (B_ROWS / ROWS_PER_CHUNK)    // 64
#define TOTAL_CTAS     (COL_BLOCKS * ROW_CHUNKS)    // 640

// Kernel-1 geometry: CTAs 0..ZERO_CTAS-1 zero accumulators, CTA ZERO_CTAS sorts
#define K1_TPB     512
#define ZERO_CTAS  40            // 40*512 = 20480 threads >= 12800 float4 per array

// Scratch (allocation-free: __device__ globals)
__device__ __align__(16) float g_sum [NUM_LABELS * CH];
__device__ __align__(16) float g_sum2[NUM_LABELS * CH];
__device__ int      g_rl[B_ROWS];       // (row << 4) | label, grouped by label
__device__ int      g_counts[NUM_LABELS];
__device__ unsigned g_done;

// ---------------------------------------------------------------------------
// Kernel 1: zero accumulators (CTAs 0..39) + counting-sort by label (CTA 40).
// Disjoint state -> safe to run in one grid.
// ---------------------------------------------------------------------------
__global__ __launch_bounds__(K1_TPB) void prep_kernel(const int* __restrict__ labels) {
    if (blockIdx.x < ZERO_CTAS) {
        // ---- zero path: one float4 store per thread per array ----
        int i = blockIdx.x * K1_TPB + threadIdx.x;          // float4 index
        const int n4 = (NUM_LABELS * CH) / 4;               // 12800
        float4 zv = make_float4(0.f, 0.f, 0.f, 0.f);
        if (i < n4) {
            ((float4*)g_sum)[i]  = zv;
            ((float4*)g_sum2)[i] = zv;
        }
        if (blockIdx.x == 0 && threadIdx.x == 0) g_done = 0u;
        return;
    }

    // ---- sort path: single CTA, 512 threads, int4 label loads ----
    __shared__ int sh_hist[NUM_LABELS];
    __shared__ int sh_off[NUM_LABELS];
    const int tid  = threadIdx.x;
    const int lane = tid & 31;
    const int4* __restrict__ lab4 = (const int4*)labels;

    if (tid < NUM_LABELS) sh_hist[tid] = 0;
    __syncthreads();

    // Histogram: 2048 int4 / 512 threads -> 4 iterations
    #pragma unroll
    for (int it = 0; it < (B_ROWS / 4) / K1_TPB; it++) {
        int4 v = lab4[it * K1_TPB + tid];
        #pragma unroll
        for (int j = 0; j < 4; j++) {
            int lab = (j == 0) ? v.x : (j == 1) ? v.y : (j == 2) ? v.z : v.w;
            unsigned mask = __match_any_sync(0xffffffffu, lab);
            if (lane == (__ffs(mask) - 1)) atomicAdd(&sh_hist[lab], __popc(mask));
        }
    }
    __syncthreads();

    if (tid == 0) {
        int acc = 0;
        #pragma unroll
        for (int k = 0; k < NUM_LABELS; k++) { sh_off[k] = acc; acc += sh_hist[k]; }
    }
    if (tid < NUM_LABELS) g_counts[tid] = sh_hist[tid];
    __syncthreads();

    // Scatter (order within a group irrelevant)
    #pragma unroll
    for (int it = 0; it < (B_ROWS / 4) / K1_TPB; it++) {
        int4 v = lab4[it * K1_TPB + tid];
        int b0 = (it * K1_TPB + tid) * 4;
        #pragma unroll
        for (int j = 0; j < 4; j++) {
            int lab = (j == 0) ? v.x : (j == 1) ? v.y : (j == 2) ? v.z : v.w;
            unsigned mask = __match_any_sync(0xffffffffu, lab);
            int leader = __ffs(mask) - 1;
            int rank   = __popc(mask & ((1u << lane) - 1u));
            int base = 0;
            if (lane == leader) base = atomicAdd(&sh_off[lab], __popc(mask));
            base = __shfl_sync(0xffffffffu, base, leader);
            g_rl[base + rank] = ((b0 + j) << 4) | lab;
        }
    }
}

// ---------------------------------------------------------------------------
// Kernel 2: one-pass segmented sum / sum-of-squares + fused finalize.
// grid = (COL_BLOCKS, ROW_CHUNKS), 128 thr, float4/thread, MLP=8.
// Last CTA to finish (completion counter) computes the scalar loss.
// ---------------------------------------------------------------------------
__device__ __forceinline__ void flush_acc(int lab, int colBase,
                                          float4& a, float4& a2) {
    int base = lab * CH + colBase;
    atomicAdd(&g_sum [base + 0], a.x);
    atomicAdd(&g_sum [base + 1], a.y);
    atomicAdd(&g_sum [base + 2], a.z);
    atomicAdd(&g_sum [base + 3], a.w);
    atomicAdd(&g_sum2[base + 0], a2.x);
    atomicAdd(&g_sum2[base + 1], a2.y);
    atomicAdd(&g_sum2[base + 2], a2.z);
    atomicAdd(&g_sum2[base + 3], a2.w);
    a  = make_float4(0.f, 0.f, 0.f, 0.f);
    a2 = make_float4(0.f, 0.f, 0.f, 0.f);
}

__global__ __launch_bounds__(TPB) void accum_kernel(const float* __restrict__ z,
                                                    float* __restrict__ out) {
    __shared__ int s_rl[ROWS_PER_CHUNK];
    __shared__ bool s_last;
    __shared__ float sh_red[TPB / 32];

    const int tid = threadIdx.x;
    const int cb  = blockIdx.x;   // column block 0..9
    const int rc  = blockIdx.y;   // row chunk   0..63

    s_rl[tid] = g_rl[rc * ROWS_PER_CHUNK + tid];
    __syncthreads();

    const float4* __restrict__ z4 = (const float4*)z;
    const int col4    = cb * (COLS_PER_CTA / 4) + tid;   // float4 index in row
    const int colBase = cb * COLS_PER_CTA + tid * 4;     // scalar column base

    float4 a  = make_float4(0.f, 0.f, 0.f, 0.f);
    float4 a2 = make_float4(0.f, 0.f, 0.f, 0.f);
    int cur = s_rl[0] & 15;

    for (int i = 0; i < ROWS_PER_CHUNK; i += 8) {
        int    rl[8];
        float4 v[8];
        #pragma unroll
        for (int u = 0; u < 8; u++) rl[u] = s_rl[i + u];
        #pragma unroll
        for (int u = 0; u < 8; u++) v[u] = z4[(rl[u] >> 4) * (CH / 4) + col4];

        #pragma unroll
        for (int u = 0; u < 8; u++) {
            int lab = rl[u] & 15;
            if (lab != cur) { flush_acc(cur, colBase, a, a2); cur = lab; }
            a.x += v[u].x; a.y += v[u].y; a.z += v[u].z; a.w += v[u].w;
            a2.x = fmaf(v[u].x, v[u].x, a2.x);
            a2.y = fmaf(v[u].y, v[u].y, a2.y);
            a2.z = fmaf(v[u].z, v[u].z, a2.z);
            a2.w = fmaf(v[u].w, v[u].w, a2.w);
        }
    }
    flush_acc(cur, colBase, a, a2);

    // ---- completion counter: last CTA runs the finalize ----
    __threadfence();                       // make our atomics globally visible
    __syncthreads();
    if (tid == 0) {
        unsigned t = atomicAdd(&g_done, 1u);
        s_last = (t == TOTAL_CTAS - 1u);
    }
    __syncthreads();
    if (!s_last) return;
    __threadfence();                       // acquire: see all CTAs' accumulators

    // Finalize: 51200 cells / 128 threads = 100 float4 cells per thread.
    // Read with .cg (L2) to avoid any stale L1 lines.
    float nf[NUM_LABELS];
    #pragma unroll
    for (int k = 0; k < NUM_LABELS; k++) nf[k] = (float)g_counts[k];

    float acc = 0.0f;
    const float4* s4 = (const float4*)g_sum;
    const float4* q4 = (const float4*)g_sum2;
    const int n4 = (NUM_LABELS * CH) / 4;               // 12800
    const int per_k = CH / 4;                           // 1280 float4 per label
    for (int i = tid; i < n4; i += TPB) {
        int k = i / per_k;
        float n = nf[k];
        if (n > 0.0f) {
            float4 s = __ldcg(&s4[i]);
            float4 q = __ldcg(&q4[i]);
            float inv = 1.0f / (n * (float)CH);
            float mp, e;
            mp = s.x / n - EPS; e  = q.x - 2.0f * mp * s.x + n * mp * mp;
            mp = s.y / n - EPS; e += q.y - 2.0f * mp * s.y + n * mp * mp;
            mp = s.z / n - EPS; e += q.z - 2.0f * mp * s.z + n * mp * mp;
            mp = s.w / n - EPS; e += q.w - 2.0f * mp * s.w + n * mp * mp;
            acc += e * inv;
        }
    }
    #pragma unroll
    for (int o = 16; o > 0; o >>= 1) acc += __shfl_down_sync(0xffffffffu, acc, o);
    if ((tid & 31) == 0) sh_red[tid >> 5] = acc;
    __syncthreads();
    if (tid < TPB / 32) {
        float v = sh_red[tid];
        #pragma unroll
        for (int o = (TPB / 64); o > 0; o >>= 1)
            v += __shfl_down_sync(0xfu, v, o);
        if (tid == 0) out[0] = v;
    }
}

// ---------------------------------------------------------------------------
extern "C" void kernel_launch(void* const* d_in, const int* in_sizes, int n_in,
                              void* d_out, int out_size) {
    const float* z      = (const float*)d_in[0];
    const int*   labels = (const int*)d_in[1];
    (void)in_sizes; (void)n_in; (void)out_size;

    prep_kernel<<<ZERO_CTAS + 1, K1_TPB>>>(labels);
    accum_kernel<<<dim3(COL_BLOCKS, ROW_CHUNKS), TPB>>>(z, (float*)d_out);
}

// round 4
// speedup vs baseline: 2.1305x; 2.1305x over previous
#include <cuda_runtime.h>

// Problem constants (z: [8192, 20, 256] f32, labels: [8192] i32, K=10)
#define NUM_LABELS 10
#define B_ROWS     8192
#define CH         5120          // C*H = 20*256
#define EPS        1e-8f

#define TPB            128       // threads per CTA in accumulate kernel
#define COLS_PER_CTA   512       // TPB * 4 (float4 per thread)
#define ROWS_PER_CHUNK 128
#define COL_BLOCKS     (CH / COLS_PER_CTA)          // 10
#define ROW_CHUNKS     (B_ROWS / ROWS_PER_CHUNK)    // 64

// Kernel-1 geometry: CTAs 0..ZERO_CTAS-1 zero accumulators, CTA ZERO_CTAS sorts
#define K1_TPB     512
#define ZERO_CTAS  40            // 40*512 = 20480 threads >= 12800 float4 per array

// Scratch (allocation-free: __device__ globals)
__device__ __align__(16) float g_sum [NUM_LABELS * CH];
__device__ __align__(16) float g_sum2[NUM_LABELS * CH];
__device__ int g_rl[B_ROWS];       // (row << 4) | label, grouped by label
__device__ int g_counts[NUM_LABELS];

// ---------------------------------------------------------------------------
// Kernel 1: zero accumulators + out[0] (CTAs 0..39), counting-sort (CTA 40).
// Disjoint state -> safe to run in one grid.
// ---------------------------------------------------------------------------
__global__ __launch_bounds__(K1_TPB) void prep_kernel(const int* __restrict__ labels,
                                                      float* __restrict__ out) {
    if (blockIdx.x < ZERO_CTAS) {
        int i = blockIdx.x * K1_TPB + threadIdx.x;          // float4 index
        const int n4 = (NUM_LABELS * CH) / 4;               // 12800
        float4 zv = make_float4(0.f, 0.f, 0.f, 0.f);
        if (i < n4) {
            ((float4*)g_sum)[i]  = zv;
            ((float4*)g_sum2)[i] = zv;
        }
        if (i == 0) out[0] = 0.0f;
        return;
    }

    // ---- sort path: single CTA, 512 threads, int4 label loads ----
    __shared__ int sh_hist[NUM_LABELS];
    __shared__ int sh_off[NUM_LABELS];
    const int tid  = threadIdx.x;
    const int lane = tid & 31;
    const int4* __restrict__ lab4 = (const int4*)labels;

    if (tid < NUM_LABELS) sh_hist[tid] = 0;
    __syncthreads();

    // Histogram: 2048 int4 / 512 threads -> 4 iterations
    #pragma unroll
    for (int it = 0; it < (B_ROWS / 4) / K1_TPB; it++) {
        int4 v = lab4[it * K1_TPB + tid];
        #pragma unroll
        for (int j = 0; j < 4; j++) {
            int lab = (j == 0) ? v.x : (j == 1) ? v.y : (j == 2) ? v.z : v.w;
            unsigned mask = __match_any_sync(0xffffffffu, lab);
            if (lane == (__ffs(mask) - 1)) atomicAdd(&sh_hist[lab], __popc(mask));
        }
    }
    __syncthreads();

    if (tid == 0) {
        int acc = 0;
        #pragma unroll
        for (int k = 0; k < NUM_LABELS; k++) { sh_off[k] = acc; acc += sh_hist[k]; }
    }
    if (tid < NUM_LABELS) g_counts[tid] = sh_hist[tid];
    __syncthreads();

    // Scatter (order within a group irrelevant)
    #pragma unroll
    for (int it = 0; it < (B_ROWS / 4) / K1_TPB; it++) {
        int4 v = lab4[it * K1_TPB + tid];
        int b0 = (it * K1_TPB + tid) * 4;
        #pragma unroll
        for (int j = 0; j < 4; j++) {
            int lab = (j == 0) ? v.x : (j == 1) ? v.y : (j == 2) ? v.z : v.w;
            unsigned mask = __match_any_sync(0xffffffffu, lab);
            int leader = __ffs(mask) - 1;
            int rank   = __popc(mask & ((1u << lane) - 1u));
            int base = 0;
            if (lane == leader) base = atomicAdd(&sh_off[lab], __popc(mask));
            base = __shfl_sync(0xffffffffu, base, leader);
            g_rl[base + rank] = ((b0 + j) << 4) | lab;
        }
    }
}

// ---------------------------------------------------------------------------
// Kernel 2: one-pass segmented sum / sum-of-squares (pure R2 body — no tail).
// grid = (COL_BLOCKS, ROW_CHUNKS), 128 threads, float4/thread, MLP=8.
// ---------------------------------------------------------------------------
__device__ __forceinline__ void flush_acc(int lab, int colBase,
                                          float4& a, float4& a2) {
    int base = lab * CH + colBase;
    atomicAdd(&g_sum [base + 0], a.x);
    atomicAdd(&g_sum [base + 1], a.y);
    atomicAdd(&g_sum [base + 2], a.z);
    atomicAdd(&g_sum [base + 3], a.w);
    atomicAdd(&g_sum2[base + 0], a2.x);
    atomicAdd(&g_sum2[base + 1], a2.y);
    atomicAdd(&g_sum2[base + 2], a2.z);
    atomicAdd(&g_sum2[base + 3], a2.w);
    a  = make_float4(0.f, 0.f, 0.f, 0.f);
    a2 = make_float4(0.f, 0.f, 0.f, 0.f);
}

__global__ __launch_bounds__(TPB) void accum_kernel(const float* __restrict__ z) {
    __shared__ int s_rl[ROWS_PER_CHUNK];
    const int tid = threadIdx.x;
    const int cb  = blockIdx.x;   // column block 0..9
    const int rc  = blockIdx.y;   // row chunk   0..63

    s_rl[tid] = g_rl[rc * ROWS_PER_CHUNK + tid];
    __syncthreads();

    const float4* __restrict__ z4 = (const float4*)z;
    const int col4    = cb * (COLS_PER_CTA / 4) + tid;   // float4 index in row
    const int colBase = cb * COLS_PER_CTA + tid * 4;     // scalar column base

    float4 a  = make_float4(0.f, 0.f, 0.f, 0.f);
    float4 a2 = make_float4(0.f, 0.f, 0.f, 0.f);
    int cur = s_rl[0] & 15;

    for (int i = 0; i < ROWS_PER_CHUNK; i += 8) {
        int    rl[8];
        float4 v[8];
        #pragma unroll
        for (int u = 0; u < 8; u++) rl[u] = s_rl[i + u];
        #pragma unroll
        for (int u = 0; u < 8; u++) v[u] = z4[(rl[u] >> 4) * (CH / 4) + col4];

        #pragma unroll
        for (int u = 0; u < 8; u++) {
            int lab = rl[u] & 15;
            if (lab != cur) { flush_acc(cur, colBase, a, a2); cur = lab; }
            a.x += v[u].x; a.y += v[u].y; a.z += v[u].z; a.w += v[u].w;
            a2.x = fmaf(v[u].x, v[u].x, a2.x);
            a2.y = fmaf(v[u].y, v[u].y, a2.y);
            a2.z = fmaf(v[u].z, v[u].z, a2.z);
            a2.w = fmaf(v[u].w, v[u].w, a2.w);
        }
    }
    flush_acc(cur, colBase, a, a2);
}

// ---------------------------------------------------------------------------
// Kernel 3: finalize.  grid = (NUM_LABELS, CH/1024), 1024 thr, 1 cell/thread.
// sse(k,j) = q - 2*m'*s + n*m'^2, m' = s/n - EPS; CTA-reduce; atomicAdd.
// (out[0] is zeroed by prep_kernel.)
// ---------------------------------------------------------------------------
__global__ __launch_bounds__(1024) void finalize_kernel(float* __restrict__ out) {
    __shared__ float sh[32];
    const int k   = blockIdx.x;
    const int j   = blockIdx.y * 1024 + threadIdx.x;
    const int tid = threadIdx.x;

    float n = (float)g_counts[k];
    float acc = 0.0f;
    if (n > 0.0f) {
        int idx  = k * CH + j;
        float s  = g_sum[idx];
        float q  = g_sum2[idx];
        float mp = s / n - EPS;
        float e  = q - 2.0f * mp * s + n * mp * mp;
        acc = e / (n * (float)CH);
    }
    #pragma unroll
    for (int o = 16; o > 0; o >>= 1) acc += __shfl_down_sync(0xffffffffu, acc, o);
    if ((tid & 31) == 0) sh[tid >> 5] = acc;
    __syncthreads();
    if (tid < 32) {
        float v = sh[tid];
        #pragma unroll
        for (int o = 16; o > 0; o >>= 1) v += __shfl_down_sync(0xffffffffu, v, o);
        if (tid == 0) atomicAdd(out, v);
    }
}

// ---------------------------------------------------------------------------
extern "C" void kernel_launch(void* const* d_in, const int* in_sizes, int n_in,
                              void* d_out, int out_size) {
    const float* z      = (const float*)d_in[0];
    const int*   labels = (const int*)d_in[1];
    (void)in_sizes; (void)n_in; (void)out_size;

    prep_kernel<<<ZERO_CTAS + 1, K1_TPB>>>(labels, (float*)d_out);
    accum_kernel<<<dim3(COL_BLOCKS, ROW_CHUNKS), TPB>>>(z);
    finalize_kernel<<<dim3(NUM_LABELS, CH / 1024), 1024>>>((float*)d_out);
}